// round 5
// baseline (speedup 1.0000x reference)
#include <cuda_runtime.h>
#include <cuda_fp16.h>
#include <cuda_bf16.h>
#include <cstdint>
#include <cstddef>

#define CN 22
#define FN 192
#define HN 128
#define BT_TOT 16384
#define NROWS (BT_TOT * CN)     // 360448 = 2048 * 176
#define TM 176                  // CTA M-tile = 8 bt-groups
#define NTHREADS 352            // 11 warps, warp tile 16 x 128

// scratch: H fp32 [NROWS,128]
__device__ float g_H[(size_t)NROWS * HN];
// weights pre-split bf16 hi/lo, MMA-fragment order: t = s*512 + f*32 + lane
__device__ uint4 g_W0s[(FN / 16) * 512];
__device__ uint4 g_W1s[(HN / 16) * 512];

// smem layout (bytes), phase A (mainloop) / phase B (epilogue) union
#define OFF_XH 0                         // uint32[176*20] hi  (14080 B)
#define OFF_XL 14080                     // uint32[176*20] lo
#define OFF_W  28160                     // uint4[1024]        (16384 B)
#define OFF_U  0                         // float[176*132]     (92928 B)
#define OFF_A  92928                     // float[8*22*24]     (16896 B)
#define SMEM_TOTAL 109824

__device__ __forceinline__ uint32_t pack_bf16(float x, float y) {
    __nv_bfloat162 p;
    p.x = __float2bfloat16(x);
    p.y = __float2bfloat16(y);
    return *reinterpret_cast<uint32_t*>(&p);
}
__device__ __forceinline__ uint32_t pack_bf16_resid(float x, float y, uint32_t hi) {
    __nv_bfloat162 h = *reinterpret_cast<__nv_bfloat162*>(&hi);
    return pack_bf16(x - __bfloat162float(h.x), y - __bfloat162float(h.y));
}

// ---- weight prep: W [128][K] fp32 -> fragment-order split bf16 ----
__global__ void prep_w(const float* __restrict__ W, int K, uint4* __restrict__ out) {
    int t = blockIdx.x * blockDim.x + threadIdx.x;
    int total = (K / 16) * 512;
    if (t >= total) return;
    int l = t & 31;
    int f = (t >> 5) & 15;
    int s = t >> 9;
    int n = f * 8 + (l >> 2);
    int k0 = s * 16 + (l & 3) * 2;
    const float* wr = W + (size_t)n * K;
    float w00 = wr[k0], w01 = wr[k0 + 1], w10 = wr[k0 + 8], w11 = wr[k0 + 9];
    uint32_t h0 = pack_bf16(w00, w01), h1 = pack_bf16(w10, w11);
    uint32_t l0 = pack_bf16_resid(w00, w01, h0), l1 = pack_bf16_resid(w10, w11, h1);
    out[t] = make_uint4(h0, h1, l0, l1);
}

// ---- mma.sync m16n8k16 row.col bf16 -> f32 ----
__device__ __forceinline__ void mma_bf16(float* c, const uint32_t* a, uint32_t b0, uint32_t b1) {
    asm volatile(
        "mma.sync.aligned.m16n8k16.row.col.f32.bf16.bf16.f32 "
        "{%0,%1,%2,%3}, {%4,%5,%6,%7}, {%8,%9}, {%0,%1,%2,%3};"
        : "+f"(c[0]), "+f"(c[1]), "+f"(c[2]), "+f"(c[3])
        : "r"(a[0]), "r"(a[1]), "r"(a[2]), "r"(a[3]), "r"(b0), "r"(b1));
}

// ---- fused: dst-layer = epilogue(A-mix(relu(src@W^T + b))) ----
// MEAN=false: write H = relu(A@U + b)   (176 rows of it)
// MEAN=true : write out = mean_c relu(A@V + b)  (8 rows of 128)
template <int K, bool MEAN>
__global__ void __launch_bounds__(NTHREADS, 1) fused_layer(
    const float* __restrict__ src, const uint4* __restrict__ Ws,
    const float* __restrict__ A, const float* __restrict__ bias,
    float* __restrict__ dst)
{
    extern __shared__ __align__(16) char sm[];
    uint32_t* sXh = reinterpret_cast<uint32_t*>(sm + OFF_XH);
    uint32_t* sXl = reinterpret_cast<uint32_t*>(sm + OFF_XL);
    uint4*    sW  = reinterpret_cast<uint4*>(sm + OFF_W);

    const int t = threadIdx.x;
    const int wid = t >> 5, l = t & 31;
    const int g = l >> 2, q = l & 3;
    const int row0 = blockIdx.x * TM;
    const int rb = wid * 16;

    float acc[16][4];
#pragma unroll
    for (int f = 0; f < 16; f++)
#pragma unroll
        for (int i = 0; i < 4; i++) acc[f][i] = 0.f;

    // staging assignment: thread -> (row r, 16-col half)
    const int r = t >> 1, half = t & 1;
    const float* xrow = src + (size_t)(row0 + r) * K + half * 16;

    float4 xv[4];
    uint4 wv[4];
#pragma unroll
    for (int i = 0; i < 4; i++) xv[i] = *reinterpret_cast<const float4*>(xrow + i * 4);
    if (t < 256) {
#pragma unroll
        for (int i = 0; i < 4; i++) wv[i] = Ws[t + i * 256];
    }

    constexpr int NC = K / 32;
#pragma unroll 1
    for (int kc = 0; kc < NC; kc++) {
        __syncthreads();   // previous chunk's fragment loads done
        // store staged chunk (convert fp32 -> split bf16)
        {
            uint32_t hi[8], lo[8];
#pragma unroll
            for (int i = 0; i < 4; i++) {
                hi[2 * i]     = pack_bf16(xv[i].x, xv[i].y);
                hi[2 * i + 1] = pack_bf16(xv[i].z, xv[i].w);
                lo[2 * i]     = pack_bf16_resid(xv[i].x, xv[i].y, hi[2 * i]);
                lo[2 * i + 1] = pack_bf16_resid(xv[i].z, xv[i].w, hi[2 * i + 1]);
            }
            int base = r * 20 + half * 8;
            *reinterpret_cast<uint4*>(&sXh[base])     = make_uint4(hi[0], hi[1], hi[2], hi[3]);
            *reinterpret_cast<uint4*>(&sXh[base + 4]) = make_uint4(hi[4], hi[5], hi[6], hi[7]);
            *reinterpret_cast<uint4*>(&sXl[base])     = make_uint4(lo[0], lo[1], lo[2], lo[3]);
            *reinterpret_cast<uint4*>(&sXl[base + 4]) = make_uint4(lo[4], lo[5], lo[6], lo[7]);
        }
        if (t < 256) {
#pragma unroll
            for (int i = 0; i < 4; i++) sW[t + i * 256] = wv[i];
        }
        __syncthreads();
        // prefetch next chunk (LDGs overlap the mma below)
        if (kc + 1 < NC) {
            const float* xp2 = xrow + (kc + 1) * 32;
#pragma unroll
            for (int i = 0; i < 4; i++) xv[i] = *reinterpret_cast<const float4*>(xp2 + i * 4);
            if (t < 256) {
#pragma unroll
                for (int i = 0; i < 4; i++) wv[i] = Ws[(kc + 1) * 1024 + t + i * 256];
            }
        }
        // mma over chunk: 2 k16 steps x 16 n-frags x 3 terms
#pragma unroll
        for (int sp = 0; sp < 2; sp++) {
            int ab = (rb + g) * 20 + sp * 8 + q;
            uint32_t ah[4] = { sXh[ab], sXh[ab + 160], sXh[ab + 4], sXh[ab + 164] };
            uint32_t al[4] = { sXl[ab], sXl[ab + 160], sXl[ab + 4], sXl[ab + 164] };
#pragma unroll
            for (int f = 0; f < 16; f++) {
                uint4 bv = sW[(sp * 16 + f) * 32 + l];
                mma_bf16(acc[f], ah, bv.x, bv.y);   // Ahi*Bhi
                mma_bf16(acc[f], al, bv.x, bv.y);   // Alo*Bhi
                mma_bf16(acc[f], ah, bv.z, bv.w);   // Ahi*Blo
            }
        }
    }

    // ---- epilogue: U tile -> smem, then CTA-local A-mix ----
    __syncthreads();
    float* sU = reinterpret_cast<float*>(sm + OFF_U);   // [176][132]
    float* sA = reinterpret_cast<float*>(sm + OFF_A);   // [8][22][24]
    {
        int rg = rb + g;
#pragma unroll
        for (int f = 0; f < 16; f++) {
            int cb = f * 8 + 2 * q;
            *reinterpret_cast<float2*>(&sU[rg * 132 + cb]) =
                make_float2(acc[f][0], acc[f][1]);
            *reinterpret_cast<float2*>(&sU[(rg + 8) * 132 + cb]) =
                make_float2(acc[f][2], acc[f][3]);
        }
    }
    const int bt0 = blockIdx.x * 8;
    const float* Ag = A + (size_t)bt0 * (CN * CN);
    for (int i = t; i < 8 * CN * CN; i += NTHREADS) {
        int gg = i / (CN * CN);
        int rem = i - gg * (CN * CN);
        int c = rem / CN;
        int j = rem - c * CN;
        sA[gg * 528 + c * 24 + j] = Ag[i];
    }
    for (int p = t; p < 8 * CN; p += NTHREADS) {   // zero j-pads
        sA[p * 24 + 22] = 0.f;
        sA[p * 24 + 23] = 0.f;
    }
    __syncthreads();

    // mix: unit u = (group gg, column h); lanes keep h consecutive
    for (int u = t; u < 1024; u += NTHREADS) {
        int gg = u >> 7, h = u & 127;
        float uu[24];
#pragma unroll
        for (int j = 0; j < CN; j++) uu[j] = sU[(gg * CN + j) * 132 + h];
        uu[22] = 0.f; uu[23] = 0.f;
        float bh = __ldg(bias + h);
        float tot = 0.f;
#pragma unroll
        for (int c = 0; c < CN; c++) {
            const float4* ar = reinterpret_cast<const float4*>(&sA[gg * 528 + c * 24]);
            float s = 0.f;
#pragma unroll
            for (int jq = 0; jq < 6; jq++) {
                float4 a4 = ar[jq];
                s = fmaf(a4.x, uu[jq * 4 + 0], s);
                s = fmaf(a4.y, uu[jq * 4 + 1], s);
                s = fmaf(a4.z, uu[jq * 4 + 2], s);
                s = fmaf(a4.w, uu[jq * 4 + 3], s);
            }
            float rv = fmaxf(s + bh, 0.f);
            if (MEAN) tot += rv;
            else dst[(size_t)(row0 + gg * CN + c) * HN + h] = rv;
        }
        if (MEAN) dst[(size_t)(bt0 + gg) * HN + h] = tot * (1.0f / 22.0f);
    }
}

// ---------------- launch ----------------
extern "C" void kernel_launch(void* const* d_in, const int* in_sizes, int n_in,
                              void* d_out, int out_size) {
    const float* x  = (const float*)d_in[0];
    const float* A  = (const float*)d_in[1];
    const float* W0 = (const float*)d_in[2];
    const float* b0 = (const float*)d_in[3];
    const float* W1 = (const float*)d_in[4];
    const float* b1 = (const float*)d_in[5];
    float* out = (float*)d_out;

    const int BT = in_sizes[1] / (CN * CN);      // 16384
    const int grid = (BT * CN) / TM;             // 2048

    void *pH = nullptr, *pW0 = nullptr, *pW1 = nullptr;
    cudaGetSymbolAddress(&pH, g_H);
    cudaGetSymbolAddress(&pW0, g_W0s);
    cudaGetSymbolAddress(&pW1, g_W1s);
    float* H = (float*)pH;
    uint4* W0s = (uint4*)pW0;
    uint4* W1s = (uint4*)pW1;

    cudaFuncSetAttribute(fused_layer<FN, false>,
                         cudaFuncAttributeMaxDynamicSharedMemorySize, SMEM_TOTAL);
    cudaFuncSetAttribute(fused_layer<HN, true>,
                         cudaFuncAttributeMaxDynamicSharedMemorySize, SMEM_TOTAL);

    const int n0 = (FN / 16) * 512;              // 6144
    const int n1 = (HN / 16) * 512;              // 4096
    prep_w<<<(n0 + 255) / 256, 256>>>(W0, FN, W0s);
    prep_w<<<(n1 + 255) / 256, 256>>>(W1, HN, W1s);

    // layer 1: H = relu(A @ (x @ W0^T) + b0)
    fused_layer<FN, false><<<grid, NTHREADS, SMEM_TOTAL>>>(x, W0s, A, b0, H);
    // layer 2: out = mean_c relu(A @ (H @ W1^T) + b1)
    fused_layer<HN, true><<<grid, NTHREADS, SMEM_TOTAL>>>(H, W1s, A, b1, out);
}

// round 7
// speedup vs baseline: 1.1596x; 1.1596x over previous
#include <cuda_runtime.h>
#include <cuda_fp16.h>
#include <cuda_bf16.h>
#include <cstdint>
#include <cstddef>

#define CN 22
#define FN 192
#define HN 128
#define BT_TOT 16384
#define NROWS (BT_TOT * CN)     // 360448 = 2048 * 176
#define TM 176                  // CTA M-tile = 8 bt-groups
#define NTHREADS 704            // 22 warps: 11 M x 2 N, warp tile 16x64

// scratch: H fp32 [NROWS,128]
__device__ float g_H[(size_t)NROWS * HN];
// weights pre-split bf16 hi/lo, MMA-fragment order: t = s*512 + f*32 + lane
__device__ uint4 g_W0s[(FN / 16) * 512];
__device__ uint4 g_W1s[(HN / 16) * 512];

// ---- smem layout ----
// mainloop: two buffers, each { XH 14080 | XL 14080 | W 16384 } = 44544 B
#define OFF_XH 0
#define OFF_XL 14080
#define OFF_W  28160
#define BUF_STRIDE 44544
// epilogue union: U [176][132] f32 (92928) | A [8][22][24] f32 (16896)
#define OFF_U 0
#define OFF_A 92928
#define SMEM_TOTAL 109824

__device__ __forceinline__ uint32_t smem_u32(const void* p) {
    uint32_t a;
    asm("{ .reg .u64 t; cvta.to.shared.u64 t, %1; cvt.u32.u64 %0, t; }" : "=r"(a) : "l"(p));
    return a;
}
#define CP_ASYNC16(dst_u32, src_gptr) \
    asm volatile("cp.async.cg.shared.global [%0], [%1], 16;" \
                 :: "r"(dst_u32), "l"(src_gptr) : "memory")
#define CP_COMMIT() asm volatile("cp.async.commit_group;" ::: "memory")
#define CP_WAIT0()  asm volatile("cp.async.wait_group 0;" ::: "memory")

__device__ __forceinline__ uint32_t pack_bf16(float x, float y) {
    __nv_bfloat162 p;
    p.x = __float2bfloat16(x);
    p.y = __float2bfloat16(y);
    return *reinterpret_cast<uint32_t*>(&p);
}
__device__ __forceinline__ uint32_t pack_bf16_resid(float x, float y, uint32_t hi) {
    __nv_bfloat162 h = *reinterpret_cast<__nv_bfloat162*>(&hi);
    return pack_bf16(x - __bfloat162float(h.x), y - __bfloat162float(h.y));
}

// ---- weight prep: W [128][K] fp32 -> fragment-order split bf16 ----
__global__ void prep_w(const float* __restrict__ W, int K, uint4* __restrict__ out) {
    int t = blockIdx.x * blockDim.x + threadIdx.x;
    int total = (K / 16) * 512;
    if (t >= total) return;
    int l = t & 31;
    int f = (t >> 5) & 15;
    int s = t >> 9;
    int n = f * 8 + (l >> 2);
    int k0 = s * 16 + (l & 3) * 2;
    const float* wr = W + (size_t)n * K;
    float w00 = wr[k0], w01 = wr[k0 + 1], w10 = wr[k0 + 8], w11 = wr[k0 + 9];
    uint32_t h0 = pack_bf16(w00, w01), h1 = pack_bf16(w10, w11);
    uint32_t l0 = pack_bf16_resid(w00, w01, h0), l1 = pack_bf16_resid(w10, w11, h1);
    out[t] = make_uint4(h0, h1, l0, l1);
}

// ---- mma.sync m16n8k16 row.col bf16 -> f32 ----
__device__ __forceinline__ void mma_bf16(float* c, const uint32_t* a, uint32_t b0, uint32_t b1) {
    asm volatile(
        "mma.sync.aligned.m16n8k16.row.col.f32.bf16.bf16.f32 "
        "{%0,%1,%2,%3}, {%4,%5,%6,%7}, {%8,%9}, {%0,%1,%2,%3};"
        : "+f"(c[0]), "+f"(c[1]), "+f"(c[2]), "+f"(c[3])
        : "r"(a[0]), "r"(a[1]), "r"(a[2]), "r"(a[3]), "r"(b0), "r"(b1));
}

// convert 8 fp32 (one thread's k-quarter) to split bf16 and store
__device__ __forceinline__ void cvt_sts(char* buf, int sr, int sq, float4 a, float4 b) {
    uint32_t* sXh = reinterpret_cast<uint32_t*>(buf + OFF_XH);
    uint32_t* sXl = reinterpret_cast<uint32_t*>(buf + OFF_XL);
    uint32_t h0 = pack_bf16(a.x, a.y), h1 = pack_bf16(a.z, a.w);
    uint32_t h2 = pack_bf16(b.x, b.y), h3 = pack_bf16(b.z, b.w);
    uint32_t l0 = pack_bf16_resid(a.x, a.y, h0), l1 = pack_bf16_resid(a.z, a.w, h1);
    uint32_t l2 = pack_bf16_resid(b.x, b.y, h2), l3 = pack_bf16_resid(b.z, b.w, h3);
    int base = sr * 20 + sq * 4;
    *reinterpret_cast<uint4*>(&sXh[base]) = make_uint4(h0, h1, h2, h3);
    *reinterpret_cast<uint4*>(&sXl[base]) = make_uint4(l0, l1, l2, l3);
}

// ---- fused layer: epilogue(A-mix(relu(src@W^T + b))) ----
template <int K, bool MEAN>
__global__ void __launch_bounds__(NTHREADS, 1) fused_layer(
    const float* __restrict__ src, const uint4* __restrict__ Ws,
    const float* __restrict__ A, const float* __restrict__ bias,
    float* __restrict__ dst)
{
    extern __shared__ __align__(16) char sm[];
    const int t = threadIdx.x;
    const int wid = t >> 5, l = t & 31;
    const int g = l >> 2, q = l & 3;
    const int wm = wid >> 1, wn = wid & 1;
    const int row0 = blockIdx.x * TM;
    const int rb = wm * 16;
    const uint32_t smbase = smem_u32(sm);

    float acc[8][4];
#pragma unroll
    for (int f = 0; f < 8; f++)
#pragma unroll
        for (int i = 0; i < 4; i++) acc[f][i] = 0.f;

    // staging role: row sr (0..175), k-quarter sq (8 floats)
    const int sr = t >> 2, sq = t & 3;
    const float* xrow = src + (size_t)(row0 + sr) * K + sq * 8;
    const char* Wg = reinterpret_cast<const char*>(Ws);

    constexpr int NC = K / 32;

    // ---- prologue: chunk 0 into buffer 0 ----
    if (t < 512) {
        CP_ASYNC16(smbase + OFF_W + t * 16, Wg + t * 16);
        CP_ASYNC16(smbase + OFF_W + (t + 512) * 16, Wg + (t + 512) * 16);
    }
    CP_COMMIT();
    {
        float4 a0 = *reinterpret_cast<const float4*>(xrow);
        float4 a1 = *reinterpret_cast<const float4*>(xrow + 4);
        cvt_sts(sm, sr, sq, a0, a1);
    }
    CP_WAIT0();
    __syncthreads();

#pragma unroll 1
    for (int kc = 0; kc < NC; kc++) {
        const int b = kc & 1;
        char* bufc = sm + b * BUF_STRIDE;
        char* bufn = sm + (b ^ 1) * BUF_STRIDE;

        // prefetch next chunk: W via cp.async, x via regs
        float4 xv0, xv1;
        if (kc + 1 < NC) {
            if (t < 512) {
                uint32_t wdst = smbase + (uint32_t)((b ^ 1) * BUF_STRIDE + OFF_W);
                const char* wsrc = Wg + (size_t)(kc + 1) * 16384;
                CP_ASYNC16(wdst + t * 16, wsrc + t * 16);
                CP_ASYNC16(wdst + (t + 512) * 16, wsrc + (t + 512) * 16);
            }
            CP_COMMIT();
            xv0 = *reinterpret_cast<const float4*>(xrow + (kc + 1) * 32);
            xv1 = *reinterpret_cast<const float4*>(xrow + (kc + 1) * 32 + 4);
        }

        // mma on current buffer
        const uint32_t* sXh = reinterpret_cast<const uint32_t*>(bufc + OFF_XH);
        const uint32_t* sXl = reinterpret_cast<const uint32_t*>(bufc + OFF_XL);
        const uint4*    sWc = reinterpret_cast<const uint4*>(bufc + OFF_W);
#pragma unroll
        for (int sp = 0; sp < 2; sp++) {
            int ab = (rb + g) * 20 + sp * 8 + q;
            uint32_t ah[4] = { sXh[ab], sXh[ab + 160], sXh[ab + 4], sXh[ab + 164] };
            uint32_t al[4] = { sXl[ab], sXl[ab + 160], sXl[ab + 4], sXl[ab + 164] };
#pragma unroll
            for (int f = 0; f < 8; f++) {
                uint4 bv = sWc[(sp * 16 + wn * 8 + f) * 32 + l];
                mma_bf16(acc[f], ah, bv.x, bv.y);   // Ahi*Bhi
                mma_bf16(acc[f], al, bv.x, bv.y);   // Alo*Bhi
                mma_bf16(acc[f], ah, bv.z, bv.w);   // Ahi*Blo
            }
        }

        // stage next x chunk into other buffer
        if (kc + 1 < NC) cvt_sts(bufn, sr, sq, xv0, xv1);
        CP_WAIT0();
        __syncthreads();
    }

    // ---- epilogue: acc -> sU, CTA-local A-mix ----
    float* sU = reinterpret_cast<float*>(sm + OFF_U);   // [176][132]
    float* sA = reinterpret_cast<float*>(sm + OFF_A);   // [8][22][24]
    {
        int rg = rb + g;
#pragma unroll
        for (int f = 0; f < 8; f++) {
            int cb = wn * 64 + f * 8 + 2 * q;
            *reinterpret_cast<float2*>(&sU[rg * 132 + cb]) =
                make_float2(acc[f][0], acc[f][1]);
            *reinterpret_cast<float2*>(&sU[(rg + 8) * 132 + cb]) =
                make_float2(acc[f][2], acc[f][3]);
        }
    }
    const int bt0 = blockIdx.x * 8;
    const float* Ag = A + (size_t)bt0 * (CN * CN);
    for (int i = t; i < 8 * CN * CN; i += NTHREADS) {
        int gg = i / (CN * CN);
        int rem = i - gg * (CN * CN);
        int c = rem / CN;
        int j = rem - c * CN;
        sA[gg * 528 + c * 24 + j] = Ag[i];
    }
    for (int p = t; p < 8 * CN; p += NTHREADS) {   // zero j-pads
        sA[p * 24 + 22] = 0.f;
        sA[p * 24 + 23] = 0.f;
    }
    __syncthreads();

    // mix: unit u = (group gg, column h); lanes keep h consecutive
    for (int u = t; u < 1024; u += NTHREADS) {
        int gg = u >> 7, h = u & 127;
        float uu[24];
#pragma unroll
        for (int j = 0; j < CN; j++) uu[j] = sU[(gg * CN + j) * 132 + h];
        uu[22] = 0.f; uu[23] = 0.f;
        float bh = __ldg(bias + h);
        float tot = 0.f;
#pragma unroll
        for (int c = 0; c < CN; c++) {
            const float4* ar = reinterpret_cast<const float4*>(&sA[gg * 528 + c * 24]);
            float s = 0.f;
#pragma unroll
            for (int jq = 0; jq < 6; jq++) {
                float4 a4 = ar[jq];
                s = fmaf(a4.x, uu[jq * 4 + 0], s);
                s = fmaf(a4.y, uu[jq * 4 + 1], s);
                s = fmaf(a4.z, uu[jq * 4 + 2], s);
                s = fmaf(a4.w, uu[jq * 4 + 3], s);
            }
            float rv = fmaxf(s + bh, 0.f);
            if (MEAN) tot += rv;
            else dst[(size_t)(row0 + gg * CN + c) * HN + h] = rv;
        }
        if (MEAN) dst[(size_t)(bt0 + gg) * HN + h] = tot * (1.0f / 22.0f);
    }
}

// ---------------- launch ----------------
extern "C" void kernel_launch(void* const* d_in, const int* in_sizes, int n_in,
                              void* d_out, int out_size) {
    const float* x  = (const float*)d_in[0];
    const float* A  = (const float*)d_in[1];
    const float* W0 = (const float*)d_in[2];
    const float* b0 = (const float*)d_in[3];
    const float* W1 = (const float*)d_in[4];
    const float* b1 = (const float*)d_in[5];
    float* out = (float*)d_out;

    const int BT = in_sizes[1] / (CN * CN);      // 16384
    const int grid = (BT * CN) / TM;             // 2048

    void *pH = nullptr, *pW0 = nullptr, *pW1 = nullptr;
    cudaGetSymbolAddress(&pH, g_H);
    cudaGetSymbolAddress(&pW0, g_W0s);
    cudaGetSymbolAddress(&pW1, g_W1s);
    float* H = (float*)pH;
    uint4* W0s = (uint4*)pW0;
    uint4* W1s = (uint4*)pW1;

    cudaFuncSetAttribute(fused_layer<FN, false>,
                         cudaFuncAttributeMaxDynamicSharedMemorySize, SMEM_TOTAL);
    cudaFuncSetAttribute(fused_layer<HN, true>,
                         cudaFuncAttributeMaxDynamicSharedMemorySize, SMEM_TOTAL);

    const int n0 = (FN / 16) * 512;              // 6144
    const int n1 = (HN / 16) * 512;              // 4096
    prep_w<<<(n0 + 255) / 256, 256>>>(W0, FN, W0s);
    prep_w<<<(n1 + 255) / 256, 256>>>(W1, HN, W1s);

    // layer 1: H = relu(A @ (x @ W0^T) + b0)
    fused_layer<FN, false><<<grid, NTHREADS, SMEM_TOTAL>>>(x, W0s, A, b0, H);
    // layer 2: out = mean_c relu(A @ (H @ W1^T) + b1)
    fused_layer<HN, true><<<grid, NTHREADS, SMEM_TOTAL>>>(H, W1s, A, b1, out);
}

// round 12
// speedup vs baseline: 1.3146x; 1.1337x over previous
#include <cuda_runtime.h>
#include <cuda_fp16.h>
#include <cuda_bf16.h>
#include <cstdint>
#include <cstddef>

#define CN 22
#define FN 192
#define HN 128
#define TM 176                  // CTA M-tile = 8 bt-groups
#define NTHREADS 704            // 22 warps: 11 M x 2 N, warp tile 16x64

// weights pre-split bf16 hi/lo, MMA-fragment order: t = s*512 + f*32 + lane
__device__ uint4 g_W0s[(FN / 16) * 512];
__device__ uint4 g_W1s[(HN / 16) * 512];

// ---- smem layout (bytes) ----
// Region R (92928 B), time-multiplexed:
//   phase1: two buffers { XH 14080 | XL 14080 | W 16384 } = 44544 each
//   phase2/4: U/V tile float[176][132]
//   phase3: two W1 chunk buffers, 16384 each
#define OFF_XH 0
#define OFF_XL 14080
#define OFF_W  28160
#define BUF_STRIDE 44544
#define OFF_U  0
// persistent:
#define OFF_A  92928            // float[8][22][24] = 16896
#define OFF_HH 109824           // uint32[176][68]  = 47872 (H hi pairs)
#define OFF_HL 157696           // uint32[176][68]  = 47872 (H lo pairs)
#define SMEM_TOTAL 205568

__device__ __forceinline__ uint32_t smem_u32(const void* p) {
    uint32_t a;
    asm("{ .reg .u64 t; cvta.to.shared.u64 t, %1; cvt.u32.u64 %0, t; }" : "=r"(a) : "l"(p));
    return a;
}
#define CP_ASYNC16(dst_u32, src_gptr) \
    asm volatile("cp.async.cg.shared.global [%0], [%1], 16;" \
                 :: "r"(dst_u32), "l"(src_gptr) : "memory")
#define CP_COMMIT() asm volatile("cp.async.commit_group;" ::: "memory")
#define CP_WAIT0()  asm volatile("cp.async.wait_group 0;" ::: "memory")

__device__ __forceinline__ uint32_t pack_bf16(float x, float y) {
    __nv_bfloat162 p;
    p.x = __float2bfloat16(x);
    p.y = __float2bfloat16(y);
    return *reinterpret_cast<uint32_t*>(&p);
}
__device__ __forceinline__ uint32_t pack_bf16_resid(float x, float y, uint32_t hi) {
    __nv_bfloat162 h = *reinterpret_cast<__nv_bfloat162*>(&hi);
    return pack_bf16(x - __bfloat162float(h.x), y - __bfloat162float(h.y));
}

// ---- weight prep: W [128][K] fp32 -> fragment-order split bf16 ----
__global__ void prep_w(const float* __restrict__ W, int K, uint4* __restrict__ out) {
    int t = blockIdx.x * blockDim.x + threadIdx.x;
    int total = (K / 16) * 512;
    if (t >= total) return;
    int l = t & 31;
    int f = (t >> 5) & 15;
    int s = t >> 9;
    int n = f * 8 + (l >> 2);
    int k0 = s * 16 + (l & 3) * 2;
    const float* wr = W + (size_t)n * K;
    float w00 = wr[k0], w01 = wr[k0 + 1], w10 = wr[k0 + 8], w11 = wr[k0 + 9];
    uint32_t h0 = pack_bf16(w00, w01), h1 = pack_bf16(w10, w11);
    uint32_t l0 = pack_bf16_resid(w00, w01, h0), l1 = pack_bf16_resid(w10, w11, h1);
    out[t] = make_uint4(h0, h1, l0, l1);
}

// ---- mma.sync m16n8k16 row.col bf16 -> f32 ----
__device__ __forceinline__ void mma_bf16(float* c, const uint32_t* a, uint32_t b0, uint32_t b1) {
    asm volatile(
        "mma.sync.aligned.m16n8k16.row.col.f32.bf16.bf16.f32 "
        "{%0,%1,%2,%3}, {%4,%5,%6,%7}, {%8,%9}, {%0,%1,%2,%3};"
        : "+f"(c[0]), "+f"(c[1]), "+f"(c[2]), "+f"(c[3])
        : "r"(a[0]), "r"(a[1]), "r"(a[2]), "r"(a[3]), "r"(b0), "r"(b1));
}

// convert 8 fp32 (one thread's k-quarter) to split bf16 and store (phase 1)
__device__ __forceinline__ void cvt_sts(char* buf, int sr, int sq, float4 a, float4 b) {
    uint32_t* sXh = reinterpret_cast<uint32_t*>(buf + OFF_XH);
    uint32_t* sXl = reinterpret_cast<uint32_t*>(buf + OFF_XL);
    uint32_t h0 = pack_bf16(a.x, a.y), h1 = pack_bf16(a.z, a.w);
    uint32_t h2 = pack_bf16(b.x, b.y), h3 = pack_bf16(b.z, b.w);
    uint32_t l0 = pack_bf16_resid(a.x, a.y, h0), l1 = pack_bf16_resid(a.z, a.w, h1);
    uint32_t l2 = pack_bf16_resid(b.x, b.y, h2), l3 = pack_bf16_resid(b.z, b.w, h3);
    int base = sr * 20 + sq * 4;
    *reinterpret_cast<uint4*>(&sXh[base]) = make_uint4(h0, h1, h2, h3);
    *reinterpret_cast<uint4*>(&sXl[base]) = make_uint4(l0, l1, l2, l3);
}

// ---- the whole network in one kernel ----
__global__ void __launch_bounds__(NTHREADS, 1) fused_all(
    const float* __restrict__ x,
    const uint4* __restrict__ W0s, const uint4* __restrict__ W1s,
    const float* __restrict__ A,
    const float* __restrict__ b0, const float* __restrict__ b1,
    float* __restrict__ out)
{
    extern __shared__ __align__(16) char sm[];
    const int t = threadIdx.x;
    const int wid = t >> 5, l = t & 31;
    const int g = l >> 2, q = l & 3;
    const int wm = wid >> 1, wn = wid & 1;
    const int rb = wm * 16;
    const int row0 = blockIdx.x * TM;
    const int bt0 = blockIdx.x * 8;
    const uint32_t smbase = smem_u32(sm);

    float*    sA  = reinterpret_cast<float*>(sm + OFF_A);
    uint32_t* sHh = reinterpret_cast<uint32_t*>(sm + OFF_HH);
    uint32_t* sHl = reinterpret_cast<uint32_t*>(sm + OFF_HL);
    float*    sU  = reinterpret_cast<float*>(sm + OFF_U);

    // ---- load A (persistent) ----
    {
        const float* Ag = A + (size_t)bt0 * (CN * CN);
        for (int i = t; i < 8 * CN * CN; i += NTHREADS) {
            int gg = i / (CN * CN);
            int rem = i - gg * (CN * CN);
            int c = rem / CN;
            int j = rem - c * CN;
            sA[gg * 528 + c * 24 + j] = Ag[i];
        }
        for (int p = t; p < 8 * CN; p += NTHREADS) {
            sA[p * 24 + 22] = 0.f;
            sA[p * 24 + 23] = 0.f;
        }
    }

    float acc[8][4];
#pragma unroll
    for (int f = 0; f < 8; f++)
#pragma unroll
        for (int i = 0; i < 4; i++) acc[f][i] = 0.f;

    // ================= phase 1: U = x @ W0^T (K=192) =================
    const int sr = t >> 2, sq = t & 3;
    const float* xrow = x + (size_t)(row0 + sr) * FN + sq * 8;
    const char* W0g = reinterpret_cast<const char*>(W0s);

    if (t < 512) {
        CP_ASYNC16(smbase + OFF_W + t * 16, W0g + t * 16);
        CP_ASYNC16(smbase + OFF_W + (t + 512) * 16, W0g + (t + 512) * 16);
    }
    CP_COMMIT();
    {
        float4 a0 = *reinterpret_cast<const float4*>(xrow);
        float4 a1 = *reinterpret_cast<const float4*>(xrow + 4);
        cvt_sts(sm, sr, sq, a0, a1);
    }
    CP_WAIT0();
    __syncthreads();

    constexpr int NC1 = FN / 32;   // 6
#pragma unroll 1
    for (int kc = 0; kc < NC1; kc++) {
        const int b = kc & 1;
        char* bufc = sm + b * BUF_STRIDE;
        char* bufn = sm + (b ^ 1) * BUF_STRIDE;

        float4 xv0, xv1;
        if (kc + 1 < NC1) {
            if (t < 512) {
                uint32_t wdst = smbase + (uint32_t)((b ^ 1) * BUF_STRIDE + OFF_W);
                const char* wsrc = W0g + (size_t)(kc + 1) * 16384;
                CP_ASYNC16(wdst + t * 16, wsrc + t * 16);
                CP_ASYNC16(wdst + (t + 512) * 16, wsrc + (t + 512) * 16);
            }
            CP_COMMIT();
            xv0 = *reinterpret_cast<const float4*>(xrow + (kc + 1) * 32);
            xv1 = *reinterpret_cast<const float4*>(xrow + (kc + 1) * 32 + 4);
        }

        const uint32_t* sXh = reinterpret_cast<const uint32_t*>(bufc + OFF_XH);
        const uint32_t* sXl = reinterpret_cast<const uint32_t*>(bufc + OFF_XL);
        const uint4*    sWc = reinterpret_cast<const uint4*>(bufc + OFF_W);
#pragma unroll
        for (int sp = 0; sp < 2; sp++) {
            int ab = (rb + g) * 20 + sp * 8 + q;
            uint32_t ah[4] = { sXh[ab], sXh[ab + 160], sXh[ab + 4], sXh[ab + 164] };
            uint32_t al[4] = { sXl[ab], sXl[ab + 160], sXl[ab + 4], sXl[ab + 164] };
#pragma unroll
            for (int f = 0; f < 8; f++) {
                uint4 bv = sWc[(sp * 16 + wn * 8 + f) * 32 + l];
                mma_bf16(acc[f], ah, bv.x, bv.y);
                mma_bf16(acc[f], al, bv.x, bv.y);
                mma_bf16(acc[f], ah, bv.z, bv.w);
            }
        }

        if (kc + 1 < NC1) cvt_sts(bufn, sr, sq, xv0, xv1);
        CP_WAIT0();
        __syncthreads();
    }

    // ================= phase 2: acc -> sU; mix1 -> H split in smem =================
    {
        int rg = rb + g;
#pragma unroll
        for (int f = 0; f < 8; f++) {
            int cb = wn * 64 + f * 8 + 2 * q;
            *reinterpret_cast<float2*>(&sU[rg * 132 + cb]) =
                make_float2(acc[f][0], acc[f][1]);
            *reinterpret_cast<float2*>(&sU[(rg + 8) * 132 + cb]) =
                make_float2(acc[f][2], acc[f][3]);
        }
    }
    __syncthreads();

    if (t < 512) {   // unit = (group gg, h-pair p)
        int gg = t >> 6, p = t & 63;
        float2 bp = *reinterpret_cast<const float2*>(b0 + 2 * p);
        float2 uu[24];
#pragma unroll
        for (int j = 0; j < CN; j++)
            uu[j] = *reinterpret_cast<const float2*>(&sU[(gg * CN + j) * 132 + 2 * p]);
        uu[22] = make_float2(0.f, 0.f);
        uu[23] = make_float2(0.f, 0.f);
#pragma unroll
        for (int c = 0; c < CN; c++) {
            const float4* ar = reinterpret_cast<const float4*>(&sA[gg * 528 + c * 24]);
            float s0 = 0.f, s1 = 0.f;
#pragma unroll
            for (int jq = 0; jq < 6; jq++) {
                float4 a4 = ar[jq];
                s0 = fmaf(a4.x, uu[jq * 4 + 0].x, s0);
                s1 = fmaf(a4.x, uu[jq * 4 + 0].y, s1);
                s0 = fmaf(a4.y, uu[jq * 4 + 1].x, s0);
                s1 = fmaf(a4.y, uu[jq * 4 + 1].y, s1);
                s0 = fmaf(a4.z, uu[jq * 4 + 2].x, s0);
                s1 = fmaf(a4.z, uu[jq * 4 + 2].y, s1);
                s0 = fmaf(a4.w, uu[jq * 4 + 3].x, s0);
                s1 = fmaf(a4.w, uu[jq * 4 + 3].y, s1);
            }
            float v0 = fmaxf(s0 + bp.x, 0.f);
            float v1 = fmaxf(s1 + bp.y, 0.f);
            uint32_t hi = pack_bf16(v0, v1);
            sHh[(gg * CN + c) * 68 + p] = hi;
            sHl[(gg * CN + c) * 68 + p] = pack_bf16_resid(v0, v1, hi);
        }
    }
    __syncthreads();

    // ================= phase 3: V = H @ W1^T (K=128), a-frags from smem =================
#pragma unroll
    for (int f = 0; f < 8; f++)
#pragma unroll
        for (int i = 0; i < 4; i++) acc[f][i] = 0.f;

    const char* W1g = reinterpret_cast<const char*>(W1s);
    if (t < 512) {
        CP_ASYNC16(smbase + t * 16, W1g + t * 16);
        CP_ASYNC16(smbase + (t + 512) * 16, W1g + (t + 512) * 16);
    }
    CP_COMMIT();
    CP_WAIT0();
    __syncthreads();

    constexpr int NC2 = HN / 32;   // 4
#pragma unroll 1
    for (int kc = 0; kc < NC2; kc++) {
        const int b = kc & 1;
        if (kc + 1 < NC2) {
            if (t < 512) {
                uint32_t wdst = smbase + (uint32_t)((b ^ 1) * 16384);
                const char* wsrc = W1g + (size_t)(kc + 1) * 16384;
                CP_ASYNC16(wdst + t * 16, wsrc + t * 16);
                CP_ASYNC16(wdst + (t + 512) * 16, wsrc + (t + 512) * 16);
            }
            CP_COMMIT();
        }
        const uint4* sWc = reinterpret_cast<const uint4*>(sm + b * 16384);
#pragma unroll
        for (int sp = 0; sp < 2; sp++) {
            int ab = (rb + g) * 68 + kc * 16 + sp * 8 + q;
            uint32_t ah[4] = { sHh[ab], sHh[ab + 544], sHh[ab + 4], sHh[ab + 548] };
            uint32_t al[4] = { sHl[ab], sHl[ab + 544], sHl[ab + 4], sHl[ab + 548] };
#pragma unroll
            for (int f = 0; f < 8; f++) {
                uint4 bv = sWc[(sp * 16 + wn * 8 + f) * 32 + l];
                mma_bf16(acc[f], ah, bv.x, bv.y);
                mma_bf16(acc[f], al, bv.x, bv.y);
                mma_bf16(acc[f], ah, bv.z, bv.w);
            }
        }
        CP_WAIT0();
        __syncthreads();
    }

    // ================= phase 4: acc -> sU; mix2 + mean -> out =================
    {
        int rg = rb + g;
#pragma unroll
        for (int f = 0; f < 8; f++) {
            int cb = wn * 64 + f * 8 + 2 * q;
            *reinterpret_cast<float2*>(&sU[rg * 132 + cb]) =
                make_float2(acc[f][0], acc[f][1]);
            *reinterpret_cast<float2*>(&sU[(rg + 8) * 132 + cb]) =
                make_float2(acc[f][2], acc[f][3]);
        }
    }
    __syncthreads();

    for (int u = t; u < 1024; u += NTHREADS) {
        int gg = u >> 7, h = u & 127;
        float uu[24];
#pragma unroll
        for (int j = 0; j < CN; j++) uu[j] = sU[(gg * CN + j) * 132 + h];
        uu[22] = 0.f; uu[23] = 0.f;
        float bh = __ldg(b1 + h);
        float tot = 0.f;
#pragma unroll
        for (int c = 0; c < CN; c++) {
            const float4* ar = reinterpret_cast<const float4*>(&sA[gg * 528 + c * 24]);
            float s = 0.f;
#pragma unroll
            for (int jq = 0; jq < 6; jq++) {
                float4 a4 = ar[jq];
                s = fmaf(a4.x, uu[jq * 4 + 0], s);
                s = fmaf(a4.y, uu[jq * 4 + 1], s);
                s = fmaf(a4.z, uu[jq * 4 + 2], s);
                s = fmaf(a4.w, uu[jq * 4 + 3], s);
            }
            tot += fmaxf(s + bh, 0.f);
        }
        out[(size_t)(bt0 + gg) * HN + h] = tot * (1.0f / 22.0f);
    }
}

// ---------------- launch ----------------
extern "C" void kernel_launch(void* const* d_in, const int* in_sizes, int n_in,
                              void* d_out, int out_size) {
    const float* x  = (const float*)d_in[0];
    const float* A  = (const float*)d_in[1];
    const float* W0 = (const float*)d_in[2];
    const float* b0 = (const float*)d_in[3];
    const float* W1 = (const float*)d_in[4];
    const float* b1 = (const float*)d_in[5];
    float* out = (float*)d_out;

    const int BT = in_sizes[1] / (CN * CN);      // 16384
    const int grid = (BT * CN) / TM;             // 2048

    void *pW0 = nullptr, *pW1 = nullptr;
    cudaGetSymbolAddress(&pW0, g_W0s);
    cudaGetSymbolAddress(&pW1, g_W1s);
    uint4* W0s = (uint4*)pW0;
    uint4* W1s = (uint4*)pW1;

    cudaFuncSetAttribute(fused_all,
                         cudaFuncAttributeMaxDynamicSharedMemorySize, SMEM_TOTAL);

    const int n0 = (FN / 16) * 512;              // 6144
    const int n1 = (HN / 16) * 512;              // 4096
    prep_w<<<(n0 + 255) / 256, 256>>>(W0, FN, W0s);
    prep_w<<<(n1 + 255) / 256, 256>>>(W1, HN, W1s);

    fused_all<<<grid, NTHREADS, SMEM_TOTAL>>>(x, W0s, W1s, A, b0, b1, out);
}